// round 1
// baseline (speedup 1.0000x reference)
#include <cuda_runtime.h>
#include <math.h>

#define B 1024
#define S 50000
#define D 128
#define H 8
#define UB 8            // users per block
#define TS 32           // source tile
#define NT2 512         // threads, main kernel
#define ROWS (UB*H)     // 64 (user,head) rows per block
#define MPAD 132        // padded row stride for sQ/sM (float4-aligned, reduces conflicts)
#define EPAD (TS+1)     // 33, conflict-free sE column reads

// scratch (allocation-free rule: device globals)
__device__ float g_Q[B*H*D];      // 4 MB : Q[b][h][e], pre-scaled by 1/sqrt(D)
__device__ float g_Mhat[B*H*D];   // 4 MB : per-head attention outputs

// ---------------------------------------------------------------------------
// Kernel 1: Q[b,h,e] = (sum_d Xu[b,d] * Wcm[h,d,e]) / sqrt(D)
// ---------------------------------------------------------------------------
__global__ void qproj_kernel(const int* __restrict__ uid,
                             const float* __restrict__ user_emb,
                             const float* __restrict__ Wcm) {
    __shared__ float sX[D];
    int b = blockIdx.x;
    int tid = threadIdx.x;
    int u = uid[b];
    if (tid < D) sX[tid] = user_emb[u * D + tid];
    __syncthreads();
    const float scale = rsqrtf((float)D);
    for (int o = tid; o < H * D; o += blockDim.x) {
        int h = o >> 7, e = o & 127;
        const float* w = Wcm + h * D * D + e;
        float acc = 0.f;
#pragma unroll 8
        for (int d = 0; d < D; d++) acc += sX[d] * w[d * D];
        g_Q[b * H * D + o] = acc * scale;
    }
}

// ---------------------------------------------------------------------------
// Kernel 2: fused scores -> exp(relu(.)*A) -> weighted sum over sources
// One block = UB users x H heads (64 rows), streams all S sources.
// No online-max needed: logits are small & non-negative (see analysis).
// ---------------------------------------------------------------------------
__global__ __launch_bounds__(NT2)
void attn_kernel(const int* __restrict__ uid,
                 const float* __restrict__ src,
                 const float* __restrict__ A_us) {
    extern __shared__ float smem[];
    float* sQ   = smem;                 // [ROWS][MPAD]
    float* sM   = sQ + ROWS * MPAD;     // [TS][MPAD]
    float* sE   = sM + TS * MPAD;       // [ROWS][EPAD]
    float* sA   = sE + ROWS * EPAD;     // [UB][TS]
    float* sSum = sA + UB * TS;         // [ROWS]
    int*   sUid = (int*)(sSum + ROWS);  // [UB]

    int tid = threadIdx.x;
    int b0  = blockIdx.x * UB;

    if (tid < UB) sUid[tid] = uid[b0 + tid];
    // load Q rows: ROWS*D floats
    for (int i = tid; i < ROWS * D; i += NT2)
        sQ[(i >> 7) * MPAD + (i & 127)] = g_Q[b0 * H * D + i];
    __syncthreads();

    // phase A mapping: 4 dots/thread -> rows r0,r0+1  x  cols t0,t0+1
    int r0 = (tid >> 4) * 2;        // 0..62 even
    int t0 = (tid & 15) * 2;        // 0..30 even
    // phase C mapping: 16 accumulators/thread -> row rc, cols [dc,dc+16)
    int rc = tid & 63;
    int dc = (tid >> 6) * 16;

    float acc[16];
#pragma unroll
    for (int i = 0; i < 16; i++) acc[i] = 0.f;
    float psum0 = 0.f, psum1 = 0.f;

    for (int s0 = 0; s0 < S; s0 += TS) {
        // ---- stage M tile [TS][D] (zero-fill tail) ----
        for (int i = tid; i < TS * (D / 4); i += NT2) {
            int t = i >> 5;
            int c = (i & 31) << 2;
            float4 v = make_float4(0.f, 0.f, 0.f, 0.f);
            if (s0 + t < S) v = *(const float4*)&src[(size_t)(s0 + t) * D + c];
            *(float4*)&sM[t * MPAD + c] = v;
        }
        // ---- stage A tile [UB][TS] ----
        if (tid < UB * TS) {
            int u = tid >> 5, t = tid & 31;
            float a = 0.f;
            if (s0 + t < S) a = A_us[(long long)sUid[u] * S + s0 + t];
            sA[u * TS + t] = a;
        }
        __syncthreads();

        // ---- phase A: P = Q . M^T, then e = exp(relu(p)*a) ----
        float p00 = 0.f, p01 = 0.f, p10 = 0.f, p11 = 0.f;
        const float* q0p = &sQ[r0 * MPAD];
        const float* q1p = &sQ[(r0 + 1) * MPAD];
        const float* m0p = &sM[t0 * MPAD];
        const float* m1p = &sM[(t0 + 1) * MPAD];
#pragma unroll
        for (int k = 0; k < D; k += 4) {
            float4 q0 = *(const float4*)(q0p + k);
            float4 q1 = *(const float4*)(q1p + k);
            float4 m0 = *(const float4*)(m0p + k);
            float4 m1 = *(const float4*)(m1p + k);
            p00 += q0.x * m0.x + q0.y * m0.y + q0.z * m0.z + q0.w * m0.w;
            p01 += q0.x * m1.x + q0.y * m1.y + q0.z * m1.z + q0.w * m1.w;
            p10 += q1.x * m0.x + q1.y * m0.y + q1.z * m0.z + q1.w * m0.w;
            p11 += q1.x * m1.x + q1.y * m1.y + q1.z * m1.z + q1.w * m1.w;
        }
        {
            int uu = r0 >> 3;  // r0 even -> r0 and r0+1 share the same user
            float a0 = sA[uu * TS + t0];
            float a1 = sA[uu * TS + t0 + 1];
            bool v0 = (s0 + t0) < S;
            bool v1 = (s0 + t0 + 1) < S;
            float e00 = v0 ? __expf(fmaxf(p00, 0.f) * a0) : 0.f;
            float e01 = v1 ? __expf(fmaxf(p01, 0.f) * a1) : 0.f;
            float e10 = v0 ? __expf(fmaxf(p10, 0.f) * a0) : 0.f;
            float e11 = v1 ? __expf(fmaxf(p11, 0.f) * a1) : 0.f;
            sE[r0 * EPAD + t0]           = e00;
            sE[r0 * EPAD + t0 + 1]       = e01;
            sE[(r0 + 1) * EPAD + t0]     = e10;
            sE[(r0 + 1) * EPAD + t0 + 1] = e11;
            psum0 += e00 + e01;
            psum1 += e10 + e11;
        }
        __syncthreads();

        // ---- phase C: acc[rc][dc..dc+15] += sum_t E[rc][t] * M[t][dc..] ----
#pragma unroll 4
        for (int t = 0; t < TS; t++) {
            float e = sE[rc * EPAD + t];
            const float* mrow = &sM[t * MPAD + dc];
#pragma unroll
            for (int j = 0; j < 4; j++) {
                float4 m = *(const float4*)(mrow + 4 * j);
                acc[4 * j + 0] += e * m.x;
                acc[4 * j + 1] += e * m.y;
                acc[4 * j + 2] += e * m.z;
                acc[4 * j + 3] += e * m.w;
            }
        }
        __syncthreads();
    }

    // ---- reduce softmax denominators across the 16 lanes sharing each row ----
#pragma unroll
    for (int off = 8; off >= 1; off >>= 1) {
        psum0 += __shfl_down_sync(0xffffffffu, psum0, off, 16);
        psum1 += __shfl_down_sync(0xffffffffu, psum1, off, 16);
    }
    if ((tid & 15) == 0) {
        sSum[r0]     = psum0;
        sSum[r0 + 1] = psum1;
    }
    __syncthreads();

    // ---- normalize + write per-head outputs ----
    float inv = 1.f / sSum[rc];
#pragma unroll
    for (int j = 0; j < 16; j++)
        g_Mhat[b0 * H * D + rc * D + dc + j] = acc[j] * inv;
}

// ---------------------------------------------------------------------------
// Kernel 3: out = elu(Mhat_cat @ W1) + Xu
// ---------------------------------------------------------------------------
__global__ void final_kernel(const int* __restrict__ uid,
                             const float* __restrict__ user_emb,
                             const float* __restrict__ W1,
                             float* __restrict__ out) {
    __shared__ float sm[H * D];
    int b = blockIdx.x;
    int tid = threadIdx.x;  // 128 threads, one output column each
    for (int i = tid; i < H * D; i += 128) sm[i] = g_Mhat[b * H * D + i];
    __syncthreads();
    float accv = 0.f;
#pragma unroll 8
    for (int i = 0; i < H * D; i++) accv += sm[i] * W1[i * D + tid];
    float e = accv > 0.f ? accv : expm1f(accv);
    out[b * D + tid] = e + user_emb[uid[b] * D + tid];
}

// ---------------------------------------------------------------------------
extern "C" void kernel_launch(void* const* d_in, const int* in_sizes, int n_in,
                              void* d_out, int out_size) {
    const int*   X_user_id = (const int*)d_in[0];
    const float* user_emb  = (const float*)d_in[1];
    const float* src       = (const float*)d_in[2];
    const float* Wcm       = (const float*)d_in[3];
    const float* W1        = (const float*)d_in[4];
    const float* A_us      = (const float*)d_in[5];
    float* out = (float*)d_out;

    size_t smem2 = (size_t)(ROWS * MPAD + TS * MPAD + ROWS * EPAD + UB * TS + ROWS) * 4 + UB * 4;
    cudaFuncSetAttribute(attn_kernel, cudaFuncAttributeMaxDynamicSharedMemorySize, (int)smem2);

    qproj_kernel<<<B, 256>>>(X_user_id, user_emb, Wcm);
    attn_kernel<<<B / UB, NT2, smem2>>>(X_user_id, src, A_us);
    final_kernel<<<B, D>>>(X_user_id, user_emb, W1, out);
}

// round 3
// speedup vs baseline: 8.6517x; 8.6517x over previous
#include <cuda_runtime.h>
#include <cuda_bf16.h>
#include <cstdint>
#include <math.h>

#define B 1024
#define S 50000
#define SPAD 50048
#define D 128
#define H 8
#define NROWS (B*H)          // 8192 rows (user,head)
#define KSPLIT 2
#define NT64 782             // SPAD/64 tiles
#define TPT (NT64/KSPLIT)    // 391 tiles per split
#define PITCH 272            // smem row pitch bytes (136 bf16) — conflict-free ldmatrix

// ---------------- device scratch ----------------
__device__ __nv_bfloat16 g_Qb[NROWS * D];     // Q rows bf16, pre-scaled by 1/sqrt(D)
__device__ __nv_bfloat16 g_Mb[SPAD * D];      // source emb bf16 (pad rows zero)
__device__ float g_Num[NROWS * D];            // raw numerators
__device__ float g_Den[NROWS];                // denominators

// ---------------- helpers ----------------
__device__ __forceinline__ uint32_t smem_u32(const void* p) {
    uint32_t a; asm("{ .reg .u64 t; cvta.to.shared.u64 t, %1; cvt.u32.u64 %0, t; }" : "=r"(a) : "l"(p));
    return a;
}
__device__ __forceinline__ void cp16(uint32_t dst, const void* src) {
    asm volatile("cp.async.cg.shared.global [%0], [%1], 16;" :: "r"(dst), "l"(src));
}
#define CP_COMMIT() asm volatile("cp.async.commit_group;")
#define CP_WAIT0()  asm volatile("cp.async.wait_group 0;")

__device__ __forceinline__ void ldsm4(uint32_t& r0, uint32_t& r1, uint32_t& r2, uint32_t& r3, uint32_t a) {
    asm volatile("ldmatrix.sync.aligned.m8n8.x4.shared.b16 {%0,%1,%2,%3}, [%4];"
                 : "=r"(r0), "=r"(r1), "=r"(r2), "=r"(r3) : "r"(a));
}
__device__ __forceinline__ void ldsm4t(uint32_t& r0, uint32_t& r1, uint32_t& r2, uint32_t& r3, uint32_t a) {
    asm volatile("ldmatrix.sync.aligned.m8n8.x4.trans.shared.b16 {%0,%1,%2,%3}, [%4];"
                 : "=r"(r0), "=r"(r1), "=r"(r2), "=r"(r3) : "r"(a));
}
__device__ __forceinline__ void mma16816(float* c, uint32_t a0, uint32_t a1, uint32_t a2, uint32_t a3,
                                         uint32_t b0, uint32_t b1) {
    asm volatile("mma.sync.aligned.m16n8k16.row.col.f32.bf16.bf16.f32 "
                 "{%0,%1,%2,%3},{%4,%5,%6,%7},{%8,%9},{%0,%1,%2,%3};"
                 : "+f"(c[0]), "+f"(c[1]), "+f"(c[2]), "+f"(c[3])
                 : "r"(a0), "r"(a1), "r"(a2), "r"(a3), "r"(b0), "r"(b1));
}
// exp(x) for x in [0, ~8] on the FMA pipe (no MUFU). |rel err| ~1e-7.
__device__ __forceinline__ float exp_pos(float x) {
    float t = x * 1.4426950408889634f;
    float fi = t + 12582912.f;                   // round-to-nearest int via magic
    int ei = __float_as_int(fi) << 23;
    float f = t - (fi - 12582912.f);             // f in [-0.5, 0.5]
    float p = 0.0013333558f;
    p = fmaf(p, f, 0.0096181291f);
    p = fmaf(p, f, 0.0555041087f);
    p = fmaf(p, f, 0.2402265069f);
    p = fmaf(p, f, 0.6931471806f);
    p = fmaf(p, f, 1.0f);
    return __int_as_float(__float_as_int(p) + ei);
}
__device__ __forceinline__ uint32_t packbf2(float lo, float hi) {
    __nv_bfloat162 v = __floats2bfloat162_rn(lo, hi);
    return *(uint32_t*)&v;
}

// ---------------- Kernel 0: zero accumulators ----------------
__global__ void zero_kernel() {
    int i = blockIdx.x * blockDim.x + threadIdx.x;
    if (i < NROWS * D) g_Num[i] = 0.f;
    if (i < NROWS) g_Den[i] = 0.f;
}

// ---------------- Kernel 1: Q projection -> bf16 ----------------
__global__ __launch_bounds__(256)
void qproj_kernel(const int* __restrict__ uid,
                  const float* __restrict__ user_emb,
                  const float* __restrict__ Wcm) {
    __shared__ float sX[8 * 132];
    __shared__ int sU[8];
    int bu = blockIdx.x * 8;
    int tid = threadIdx.x;
    if (tid < 8) sU[tid] = uid[bu + tid];
    __syncthreads();
    for (int i = tid; i < 8 * 128; i += 256) {
        int u = i >> 7, d = i & 127;
        sX[u * 132 + d] = user_emb[(size_t)sU[u] * D + d];
    }
    __syncthreads();
    const float scale = rsqrtf(128.f);
    for (int o = tid; o < H * D; o += 256) {
        int h = o >> 7, e = o & 127;
        const float* w = Wcm + h * D * D + e;
        float acc[8];
#pragma unroll
        for (int u = 0; u < 8; u++) acc[u] = 0.f;
#pragma unroll 4
        for (int d = 0; d < D; d++) {
            float wv = w[d * D];
#pragma unroll
            for (int u = 0; u < 8; u++) acc[u] += sX[u * 132 + d] * wv;
        }
#pragma unroll
        for (int u = 0; u < 8; u++)
            g_Qb[((size_t)(bu + u) * H + h) * D + e] = __float2bfloat16(acc[u] * scale);
    }
}

// ---------------- Kernel 2: source emb fp32 -> bf16 (pad rows zero) ----------------
__global__ __launch_bounds__(256)
void convert_kernel(const float* __restrict__ src) {
    long long i = (long long)blockIdx.x * blockDim.x + threadIdx.x;   // one float4 per thread
    if (i >= (long long)SPAD * 32) return;
    int s = (int)(i >> 5);
    int c = (int)(i & 31) << 2;
    float4 v = make_float4(0.f, 0.f, 0.f, 0.f);
    if (s < S) v = *(const float4*)&src[(size_t)s * D + c];
    *(__nv_bfloat162*)&g_Mb[(size_t)s * D + c]     = __floats2bfloat162_rn(v.x, v.y);
    *(__nv_bfloat162*)&g_Mb[(size_t)s * D + c + 2] = __floats2bfloat162_rn(v.z, v.w);
}

// ---------------- attention tile body ----------------
template<bool TAIL>
__device__ __forceinline__ void tile_body(uint32_t sqA, uint32_t srcb,
                                          const float* a0p, const float* a1p,
                                          int s0c, float (&oacc)[16][4],
                                          float& esum0, float& esum1,
                                          uint32_t b1o, uint32_t vo) {
    // ---- GEMM1: P[16 x 64] = Q[16 x 128] . Mtile^T ----
    float pa[8][4];
#pragma unroll
    for (int n = 0; n < 8; n++)
#pragma unroll
        for (int q = 0; q < 4; q++) pa[n][q] = 0.f;
#pragma unroll
    for (int k = 0; k < 8; k++) {
        uint32_t q0, q1, q2, q3;
        ldsm4(q0, q1, q2, q3, sqA + k * 32);
#pragma unroll
        for (int j = 0; j < 4; j++) {
            uint32_t b0, b1, b2, b3;
            ldsm4(b0, b1, b2, b3, srcb + b1o + j * (16 * PITCH) + k * 32);
            mma16816(pa[2 * j],     q0, q1, q2, q3, b0, b1);
            mma16816(pa[2 * j + 1], q0, q1, q2, q3, b2, b3);
        }
    }
    // ---- epilogue: e = exp(relu(p) * a), pack to bf16 A-fragments ----
    uint32_t er[4][4];
#pragma unroll
    for (int n = 0; n < 8; n++) {
        float2 a0 = *(const float2*)(a0p + 8 * n);
        float2 a1 = *(const float2*)(a1p + 8 * n);
        float e00 = exp_pos(fmaxf(pa[n][0], 0.f) * a0.x);
        float e01 = exp_pos(fmaxf(pa[n][1], 0.f) * a0.y);
        float e10 = exp_pos(fmaxf(pa[n][2], 0.f) * a1.x);
        float e11 = exp_pos(fmaxf(pa[n][3], 0.f) * a1.y);
        if (TAIL) {
            bool v0 = (s0c + 8 * n) < S;
            bool v1 = (s0c + 8 * n + 1) < S;
            e00 = v0 ? e00 : 0.f;  e01 = v1 ? e01 : 0.f;
            e10 = v0 ? e10 : 0.f;  e11 = v1 ? e11 : 0.f;
        }
        esum0 += e00 + e01;
        esum1 += e10 + e11;
        er[n >> 1][(n & 1) * 2 + 0] = packbf2(e00, e01);
        er[n >> 1][(n & 1) * 2 + 1] = packbf2(e10, e11);
    }
    // ---- GEMM2: O[16 x 128] += E[16 x 64] . Mtile ----
#pragma unroll
    for (int kk = 0; kk < 4; kk++) {
#pragma unroll
        for (int j = 0; j < 8; j++) {
            uint32_t v0, v1, v2, v3;
            ldsm4t(v0, v1, v2, v3, srcb + vo + kk * (16 * PITCH) + j * 32);
            mma16816(oacc[2 * j],     er[kk][0], er[kk][1], er[kk][2], er[kk][3], v0, v1);
            mma16816(oacc[2 * j + 1], er[kk][0], er[kk][1], er[kk][2], er[kk][3], v2, v3);
        }
    }
}

// ---------------- Kernel 3: fused attention (mma.sync bf16) ----------------
// grid (KSPLIT, 128); 128 threads. Block = 64 rows (8 users x 8 heads) x S-chunk.
#define SQ_OFF   0u
#define SRC0_OFF 17408u
#define SRC1_OFF 34816u
#define SA0_OFF  52224u
#define SA1_OFF  54400u
#define SUID_OFF 56576u
#define SMEM_BYTES 56704u

__global__ __launch_bounds__(128)
void attn_kernel(const int* __restrict__ uid, const float* __restrict__ A_us) {
    extern __shared__ char sm[];
    const uint32_t sb = smem_u32(sm);
    const int tid = threadIdx.x;
    const int lane = tid & 31;
    const int w = tid >> 5;
    const int ks = blockIdx.x;
    const int rb = blockIdx.y;
    const int rowbase = rb * 64;
    int* sUid = (int*)(sm + SUID_OFF);

    if (tid < 8) sUid[tid] = uid[rb * 8 + tid];
    __syncthreads();

    // stage Q slab [64 rows][128] bf16 into pitch-272 smem
#pragma unroll
    for (int j = 0; j < 8; j++) {
        int idx = tid + j * 128;
        int row = idx >> 4, ch = idx & 15;
        uint4 v = *(const uint4*)&g_Qb[(size_t)(rowbase + row) * D + ch * 8];
        *(uint4*)(sm + SQ_OFF + row * PITCH + ch * 16) = v;
    }

    const int t0 = ks * TPT, t1 = t0 + TPT;

    // prefetch tile t0 into buf0
    {
        int s0 = t0 * 64;
#pragma unroll
        for (int j = 0; j < 8; j++) {
            int idx = tid + j * 128;
            int row = idx >> 4, ch = idx & 15;
            cp16(sb + SRC0_OFF + row * PITCH + ch * 16, &g_Mb[(size_t)(s0 + row) * D + ch * 8]);
        }
        int u = tid >> 4, cc = (tid & 15) * 4;
        if (s0 + cc + 4 <= S)
            cp16(sb + SA0_OFF + u * PITCH + cc * 4, &A_us[(size_t)sUid[u] * S + s0 + cc]);
        CP_COMMIT();
    }

    // per-thread ldmatrix address components
    const uint32_t sqA = sb + SQ_OFF + (16 * w + (lane & 15)) * PITCH + (lane >> 4) * 16;
    const uint32_t b1o = (((lane >> 4) & 1) * 8 + (lane & 7)) * PITCH + ((lane >> 3) & 1) * 16;
    const uint32_t vo  = (((lane >> 3) & 1) * 8 + (lane & 7)) * PITCH + (lane >> 4) * 16;
    const int cb = 2 * (lane & 3);

    float oacc[16][4];
#pragma unroll
    for (int n = 0; n < 16; n++)
#pragma unroll
        for (int q = 0; q < 4; q++) oacc[n][q] = 0.f;
    float esum0 = 0.f, esum1 = 0.f;

    for (int t = t0; t < t1; ++t) {
        int bufi = (t - t0) & 1;
        CP_WAIT0();
        __syncthreads();
        if (t + 1 < t1) {   // prefetch next tile into the other buffer
            int s0n = (t + 1) * 64;
            uint32_t srcn = sb + (bufi ? SRC0_OFF : SRC1_OFF);
            uint32_t san  = sb + (bufi ? SA0_OFF : SA1_OFF);
#pragma unroll
            for (int j = 0; j < 8; j++) {
                int idx = tid + j * 128;
                int row = idx >> 4, ch = idx & 15;
                cp16(srcn + row * PITCH + ch * 16, &g_Mb[(size_t)(s0n + row) * D + ch * 8]);
            }
            int u = tid >> 4, cc = (tid & 15) * 4;
            if (s0n + cc + 4 <= S)
                cp16(san + u * PITCH + cc * 4, &A_us[(size_t)sUid[u] * S + s0n + cc]);
            CP_COMMIT();
        }
        uint32_t srcb = sb + (bufi ? SRC1_OFF : SRC0_OFF);
        const float* sAa = (const float*)(sm + (bufi ? SA1_OFF : SA0_OFF));
        const float* a0p = sAa + (2 * w) * 68 + cb;       // user 2w  (rows 0-7 of warp slab)
        const float* a1p = a0p + 68;                      // user 2w+1 (rows 8-15)
        int s0 = t * 64;
        if (t == NT64 - 1)
            tile_body<true >(sqA, srcb, a0p, a1p, s0 + cb, oacc, esum0, esum1, b1o, vo);
        else
            tile_body<false>(sqA, srcb, a0p, a1p, s0 + cb, oacc, esum0, esum1, b1o, vo);
    }

    // ---- denominators: reduce over the 4 lanes sharing each row ----
    esum0 += __shfl_xor_sync(0xffffffffu, esum0, 1);
    esum0 += __shfl_xor_sync(0xffffffffu, esum0, 2);
    esum1 += __shfl_xor_sync(0xffffffffu, esum1, 1);
    esum1 += __shfl_xor_sync(0xffffffffu, esum1, 2);
    int r0g = rowbase + 16 * w + (lane >> 2);
    if ((lane & 3) == 0) {
        atomicAdd(&g_Den[r0g], esum0);
        atomicAdd(&g_Den[r0g + 8], esum1);
    }
    // ---- raw numerators ----
#pragma unroll
    for (int nn = 0; nn < 16; nn++) {
        int c = 8 * nn + cb;
        float* d0 = &g_Num[(size_t)r0g * D + c];
        float* d1 = &g_Num[(size_t)(r0g + 8) * D + c];
        atomicAdd(d0,     oacc[nn][0]);
        atomicAdd(d0 + 1, oacc[nn][1]);
        atomicAdd(d1,     oacc[nn][2]);
        atomicAdd(d1 + 1, oacc[nn][3]);
    }
}

// ---------------- Kernel 4: normalize, W1, elu, +Xu ----------------
__global__ __launch_bounds__(128)
void final_kernel(const int* __restrict__ uid,
                  const float* __restrict__ user_emb,
                  const float* __restrict__ W1,
                  float* __restrict__ out) {
    __shared__ float smc[8 * 1024];
    int bu = blockIdx.x * 8;
    int tid = threadIdx.x;
    for (int i = tid; i < 8 * 1024; i += 128) {
        int uu = i >> 10, idx = i & 1023;
        smc[i] = g_Num[(size_t)(bu + uu) * 1024 + idx] / g_Den[(bu + uu) * 8 + (idx >> 7)];
    }
    __syncthreads();
    float acc[8];
#pragma unroll
    for (int uu = 0; uu < 8; uu++) acc[uu] = 0.f;
#pragma unroll 4
    for (int i = 0; i < 1024; i++) {
        float wv = W1[i * D + tid];
#pragma unroll
        for (int uu = 0; uu < 8; uu++) acc[uu] += smc[uu * 1024 + i] * wv;
    }
#pragma unroll
    for (int uu = 0; uu < 8; uu++) {
        float v = acc[uu];
        float e = v > 0.f ? v : expm1f(v);
        out[(size_t)(bu + uu) * D + tid] = e + user_emb[(size_t)uid[bu + uu] * D + tid];
    }
}

// ---------------------------------------------------------------------------
extern "C" void kernel_launch(void* const* d_in, const int* in_sizes, int n_in,
                              void* d_out, int out_size) {
    const int*   X_user_id = (const int*)d_in[0];
    const float* user_emb  = (const float*)d_in[1];
    const float* src       = (const float*)d_in[2];
    const float* Wcm       = (const float*)d_in[3];
    const float* W1        = (const float*)d_in[4];
    const float* A_us      = (const float*)d_in[5];
    float* out = (float*)d_out;

    cudaFuncSetAttribute(attn_kernel, cudaFuncAttributeMaxDynamicSharedMemorySize, SMEM_BYTES);

    zero_kernel<<<(NROWS * D + 1023) / 1024, 1024>>>();
    qproj_kernel<<<B / 8, 256>>>(X_user_id, user_emb, Wcm);
    convert_kernel<<<(SPAD * 32 + 255) / 256, 256>>>(src);
    attn_kernel<<<dim3(KSPLIT, NROWS / 64), 128, SMEM_BYTES>>>(X_user_id, A_us);
    final_kernel<<<B / 8, 128>>>(X_user_id, user_emb, W1, out);
}

// round 4
// speedup vs baseline: 14.8141x; 1.7123x over previous
#include <cuda_runtime.h>
#include <cuda_bf16.h>
#include <cstdint>
#include <math.h>

#define B 1024
#define S 50000
#define SPAD 50048
#define D 128
#define H 8
#define NROWS (B*H)          // 8192 rows (user,head)
#define KSPLIT 4
#define NT64 782             // SPAD/64 tiles
#define TPT ((NT64 + KSPLIT - 1)/KSPLIT)   // 196 tiles per split
#define PITCH 272            // smem row pitch bytes (136 bf16) — conflict-free ldmatrix

// ---------------- device scratch ----------------
__device__ __nv_bfloat16 g_Qb[NROWS * D];     // Q rows bf16, pre-scaled by 1/sqrt(D)
__device__ __nv_bfloat16 g_Mb[SPAD * D];      // source emb bf16 (pad rows zero)
__device__ float g_Num[NROWS * D];            // raw numerators
__device__ float g_Den[NROWS];                // denominators

// ---------------- helpers ----------------
__device__ __forceinline__ uint32_t smem_u32(const void* p) {
    uint32_t a; asm("{ .reg .u64 t; cvta.to.shared.u64 t, %1; cvt.u32.u64 %0, t; }" : "=r"(a) : "l"(p));
    return a;
}
__device__ __forceinline__ void cp16(uint32_t dst, const void* src) {
    asm volatile("cp.async.cg.shared.global [%0], [%1], 16;" :: "r"(dst), "l"(src));
}
#define CP_COMMIT() asm volatile("cp.async.commit_group;")
#define CP_WAIT0()  asm volatile("cp.async.wait_group 0;")

__device__ __forceinline__ void ldsm4(uint32_t& r0, uint32_t& r1, uint32_t& r2, uint32_t& r3, uint32_t a) {
    asm volatile("ldmatrix.sync.aligned.m8n8.x4.shared.b16 {%0,%1,%2,%3}, [%4];"
                 : "=r"(r0), "=r"(r1), "=r"(r2), "=r"(r3) : "r"(a));
}
__device__ __forceinline__ void ldsm4t(uint32_t& r0, uint32_t& r1, uint32_t& r2, uint32_t& r3, uint32_t a) {
    asm volatile("ldmatrix.sync.aligned.m8n8.x4.trans.shared.b16 {%0,%1,%2,%3}, [%4];"
                 : "=r"(r0), "=r"(r1), "=r"(r2), "=r"(r3) : "r"(a));
}
__device__ __forceinline__ void mma16816(float* c, uint32_t a0, uint32_t a1, uint32_t a2, uint32_t a3,
                                         uint32_t b0, uint32_t b1) {
    asm volatile("mma.sync.aligned.m16n8k16.row.col.f32.bf16.bf16.f32 "
                 "{%0,%1,%2,%3},{%4,%5,%6,%7},{%8,%9},{%0,%1,%2,%3};"
                 : "+f"(c[0]), "+f"(c[1]), "+f"(c[2]), "+f"(c[3])
                 : "r"(a0), "r"(a1), "r"(a2), "r"(a3), "r"(b0), "r"(b1));
}
// exp(x) for x in [0, ~8] on the FMA pipe (no MUFU). |rel err| ~1e-7.
__device__ __forceinline__ float exp_pos(float x) {
    float t = x * 1.4426950408889634f;
    float fi = t + 12582912.f;                   // round-to-nearest int via magic
    int ei = __float_as_int(fi) << 23;
    float f = t - (fi - 12582912.f);             // f in [-0.5, 0.5]
    float p = 0.0013333558f;
    p = fmaf(p, f, 0.0096181291f);
    p = fmaf(p, f, 0.0555041087f);
    p = fmaf(p, f, 0.2402265069f);
    p = fmaf(p, f, 0.6931471806f);
    p = fmaf(p, f, 1.0f);
    return __int_as_float(__float_as_int(p) + ei);
}
__device__ __forceinline__ uint32_t packbf2(float lo, float hi) {
    __nv_bfloat162 v = __floats2bfloat162_rn(lo, hi);
    return *(uint32_t*)&v;
}

// ---------------- Kernel 0: zero accumulators ----------------
__global__ void zero_kernel() {
    int i = blockIdx.x * blockDim.x + threadIdx.x;
    if (i < NROWS * D) g_Num[i] = 0.f;
    if (i < NROWS) g_Den[i] = 0.f;
}

// ---------------- Kernel 1: Q projection -> bf16 ----------------
__global__ __launch_bounds__(256)
void qproj_kernel(const int* __restrict__ uid,
                  const float* __restrict__ user_emb,
                  const float* __restrict__ Wcm) {
    __shared__ float sX[8 * 132];
    __shared__ int sU[8];
    int bu = blockIdx.x * 8;
    int tid = threadIdx.x;
    if (tid < 8) sU[tid] = uid[bu + tid];
    __syncthreads();
    for (int i = tid; i < 8 * 128; i += 256) {
        int u = i >> 7, d = i & 127;
        sX[u * 132 + d] = user_emb[(size_t)sU[u] * D + d];
    }
    __syncthreads();
    const float scale = rsqrtf(128.f);
    for (int o = tid; o < H * D; o += 256) {
        int h = o >> 7, e = o & 127;
        const float* w = Wcm + h * D * D + e;
        float acc[8];
#pragma unroll
        for (int u = 0; u < 8; u++) acc[u] = 0.f;
#pragma unroll 4
        for (int d = 0; d < D; d++) {
            float wv = w[d * D];
#pragma unroll
            for (int u = 0; u < 8; u++) acc[u] += sX[u * 132 + d] * wv;
        }
#pragma unroll
        for (int u = 0; u < 8; u++)
            g_Qb[((size_t)(bu + u) * H + h) * D + e] = __float2bfloat16(acc[u] * scale);
    }
}

// ---------------- Kernel 2: source emb fp32 -> bf16 (pad rows zero) ----------------
__global__ __launch_bounds__(256)
void convert_kernel(const float* __restrict__ src) {
    long long i = (long long)blockIdx.x * blockDim.x + threadIdx.x;   // one float4 per thread
    if (i >= (long long)SPAD * 32) return;
    int s = (int)(i >> 5);
    int c = (int)(i & 31) << 2;
    float4 v = make_float4(0.f, 0.f, 0.f, 0.f);
    if (s < S) v = *(const float4*)&src[(size_t)s * D + c];
    *(__nv_bfloat162*)&g_Mb[(size_t)s * D + c]     = __floats2bfloat162_rn(v.x, v.y);
    *(__nv_bfloat162*)&g_Mb[(size_t)s * D + c + 2] = __floats2bfloat162_rn(v.z, v.w);
}

// ---------------- attention tile body ----------------
template<bool TAIL>
__device__ __forceinline__ void tile_body(uint32_t sqA, uint32_t srcb,
                                          const float* a0p, const float* a1p,
                                          int s0c, float (&oacc)[16][4],
                                          float& esum0, float& esum1,
                                          uint32_t b1o, uint32_t vo) {
    // ---- GEMM1: P[16 x 64] = Q[16 x 128] . Mtile^T ----
    float pa[8][4];
#pragma unroll
    for (int n = 0; n < 8; n++)
#pragma unroll
        for (int q = 0; q < 4; q++) pa[n][q] = 0.f;
#pragma unroll
    for (int k = 0; k < 8; k++) {
        uint32_t q0, q1, q2, q3;
        ldsm4(q0, q1, q2, q3, sqA + k * 32);
#pragma unroll
        for (int j = 0; j < 4; j++) {
            uint32_t b0, b1, b2, b3;
            ldsm4(b0, b1, b2, b3, srcb + b1o + j * (16 * PITCH) + k * 32);
            mma16816(pa[2 * j],     q0, q1, q2, q3, b0, b1);
            mma16816(pa[2 * j + 1], q0, q1, q2, q3, b2, b3);
        }
    }
    // ---- epilogue: e = exp(relu(p) * a), pack to bf16 A-fragments ----
    uint32_t er[4][4];
#pragma unroll
    for (int n = 0; n < 8; n++) {
        float2 a0 = *(const float2*)(a0p + 8 * n);
        float2 a1 = *(const float2*)(a1p + 8 * n);
        float e00 = exp_pos(fmaxf(pa[n][0], 0.f) * a0.x);
        float e01 = exp_pos(fmaxf(pa[n][1], 0.f) * a0.y);
        float e10 = exp_pos(fmaxf(pa[n][2], 0.f) * a1.x);
        float e11 = exp_pos(fmaxf(pa[n][3], 0.f) * a1.y);
        if (TAIL) {
            bool v0 = (s0c + 8 * n) < S;
            bool v1 = (s0c + 8 * n + 1) < S;
            e00 = v0 ? e00 : 0.f;  e01 = v1 ? e01 : 0.f;
            e10 = v0 ? e10 : 0.f;  e11 = v1 ? e11 : 0.f;
        }
        esum0 += e00 + e01;
        esum1 += e10 + e11;
        er[n >> 1][(n & 1) * 2 + 0] = packbf2(e00, e01);
        er[n >> 1][(n & 1) * 2 + 1] = packbf2(e10, e11);
    }
    // ---- GEMM2: O[16 x 128] += E[16 x 64] . Mtile ----
#pragma unroll
    for (int kk = 0; kk < 4; kk++) {
#pragma unroll
        for (int j = 0; j < 8; j++) {
            uint32_t v0, v1, v2, v3;
            ldsm4t(v0, v1, v2, v3, srcb + vo + kk * (16 * PITCH) + j * 32);
            mma16816(oacc[2 * j],     er[kk][0], er[kk][1], er[kk][2], er[kk][3], v0, v1);
            mma16816(oacc[2 * j + 1], er[kk][0], er[kk][1], er[kk][2], er[kk][3], v2, v3);
        }
    }
}

// ---------------- Kernel 3: fused attention (mma.sync bf16) ----------------
// grid (KSPLIT, 128); 128 threads. Block = 64 rows (8 users x 8 heads) x S-chunk.
#define SQ_OFF   0u
#define SRC0_OFF 17408u
#define SRC1_OFF 34816u
#define SA0_OFF  52224u
#define SA1_OFF  54400u
#define SUID_OFF 56576u
#define SMEM_BYTES 56704u

__global__ __launch_bounds__(128, 4)
void attn_kernel(const int* __restrict__ uid, const float* __restrict__ A_us) {
    extern __shared__ char sm[];
    const uint32_t sb = smem_u32(sm);
    const int tid = threadIdx.x;
    const int lane = tid & 31;
    const int w = tid >> 5;
    const int ks = blockIdx.x;
    const int rb = blockIdx.y;
    const int rowbase = rb * 64;
    int* sUid = (int*)(sm + SUID_OFF);

    if (tid < 8) sUid[tid] = uid[rb * 8 + tid];
    __syncthreads();

    // stage Q slab [64 rows][128] bf16 into pitch-272 smem
#pragma unroll
    for (int j = 0; j < 8; j++) {
        int idx = tid + j * 128;
        int row = idx >> 4, ch = idx & 15;
        uint4 v = *(const uint4*)&g_Qb[(size_t)(rowbase + row) * D + ch * 8];
        *(uint4*)(sm + SQ_OFF + row * PITCH + ch * 16) = v;
    }

    const int t0 = ks * TPT;
    const int t1 = min(t0 + TPT, NT64);

    // prefetch tile t0 into buf0
    {
        int s0 = t0 * 64;
#pragma unroll
        for (int j = 0; j < 8; j++) {
            int idx = tid + j * 128;
            int row = idx >> 4, ch = idx & 15;
            cp16(sb + SRC0_OFF + row * PITCH + ch * 16, &g_Mb[(size_t)(s0 + row) * D + ch * 8]);
        }
        int u = tid >> 4, cc = (tid & 15) * 4;
        if (s0 + cc + 4 <= S)
            cp16(sb + SA0_OFF + u * PITCH + cc * 4, &A_us[(size_t)sUid[u] * S + s0 + cc]);
        CP_COMMIT();
    }

    // per-thread ldmatrix address components
    const uint32_t sqA = sb + SQ_OFF + (16 * w + (lane & 15)) * PITCH + (lane >> 4) * 16;
    const uint32_t b1o = (((lane >> 4) & 1) * 8 + (lane & 7)) * PITCH + ((lane >> 3) & 1) * 16;
    const uint32_t vo  = (((lane >> 3) & 1) * 8 + (lane & 7)) * PITCH + (lane >> 4) * 16;
    const int cb = 2 * (lane & 3);

    float oacc[16][4];
#pragma unroll
    for (int n = 0; n < 16; n++)
#pragma unroll
        for (int q = 0; q < 4; q++) oacc[n][q] = 0.f;
    float esum0 = 0.f, esum1 = 0.f;

    for (int t = t0; t < t1; ++t) {
        int bufi = (t - t0) & 1;
        CP_WAIT0();
        __syncthreads();
        if (t + 1 < t1) {   // prefetch next tile into the other buffer
            int s0n = (t + 1) * 64;
            uint32_t srcn = sb + (bufi ? SRC0_OFF : SRC1_OFF);
            uint32_t san  = sb + (bufi ? SA0_OFF : SA1_OFF);
#pragma unroll
            for (int j = 0; j < 8; j++) {
                int idx = tid + j * 128;
                int row = idx >> 4, ch = idx & 15;
                cp16(srcn + row * PITCH + ch * 16, &g_Mb[(size_t)(s0n + row) * D + ch * 8]);
            }
            int u = tid >> 4, cc = (tid & 15) * 4;
            if (s0n + cc + 4 <= S)
                cp16(san + u * PITCH + cc * 4, &A_us[(size_t)sUid[u] * S + s0n + cc]);
            CP_COMMIT();
        }
        uint32_t srcb = sb + (bufi ? SRC1_OFF : SRC0_OFF);
        const float* sAa = (const float*)(sm + (bufi ? SA1_OFF : SA0_OFF));
        const float* a0p = sAa + (2 * w) * 68 + cb;       // user 2w  (rows 0-7 of warp slab)
        const float* a1p = a0p + 68;                      // user 2w+1 (rows 8-15)
        int s0 = t * 64;
        if (t == NT64 - 1)
            tile_body<true >(sqA, srcb, a0p, a1p, s0 + cb, oacc, esum0, esum1, b1o, vo);
        else
            tile_body<false>(sqA, srcb, a0p, a1p, s0 + cb, oacc, esum0, esum1, b1o, vo);
    }

    // ---- denominators: reduce over the 4 lanes sharing each row ----
    esum0 += __shfl_xor_sync(0xffffffffu, esum0, 1);
    esum0 += __shfl_xor_sync(0xffffffffu, esum0, 2);
    esum1 += __shfl_xor_sync(0xffffffffu, esum1, 1);
    esum1 += __shfl_xor_sync(0xffffffffu, esum1, 2);
    int r0g = rowbase + 16 * w + (lane >> 2);
    if ((lane & 3) == 0) {
        atomicAdd(&g_Den[r0g], esum0);
        atomicAdd(&g_Den[r0g + 8], esum1);
    }
    // ---- raw numerators ----
#pragma unroll
    for (int nn = 0; nn < 16; nn++) {
        int c = 8 * nn + cb;
        float* d0 = &g_Num[(size_t)r0g * D + c];
        float* d1 = &g_Num[(size_t)(r0g + 8) * D + c];
        atomicAdd(d0,     oacc[nn][0]);
        atomicAdd(d0 + 1, oacc[nn][1]);
        atomicAdd(d1,     oacc[nn][2]);
        atomicAdd(d1 + 1, oacc[nn][3]);
    }
}

// ---------------- Kernel 4: normalize, W1, elu, +Xu ----------------
__global__ __launch_bounds__(128)
void final_kernel(const int* __restrict__ uid,
                  const float* __restrict__ user_emb,
                  const float* __restrict__ W1,
                  float* __restrict__ out) {
    __shared__ float smc[8 * 1024];
    int bu = blockIdx.x * 8;
    int tid = threadIdx.x;
    for (int i = tid; i < 8 * 1024; i += 128) {
        int uu = i >> 10, idx = i & 1023;
        smc[i] = g_Num[(size_t)(bu + uu) * 1024 + idx] / g_Den[(bu + uu) * 8 + (idx >> 7)];
    }
    __syncthreads();
    float acc[8];
#pragma unroll
    for (int uu = 0; uu < 8; uu++) acc[uu] = 0.f;
#pragma unroll 4
    for (int i = 0; i < 1024; i++) {
        float wv = W1[i * D + tid];
#pragma unroll
        for (int uu = 0; uu < 8; uu++) acc[uu] += smc[uu * 1024 + i] * wv;
    }
#pragma unroll
    for (int uu = 0; uu < 8; uu++) {
        float v = acc[uu];
        float e = v > 0.f ? v : expm1f(v);
        out[(size_t)(bu + uu) * D + tid] = e + user_emb[(size_t)uid[bu + uu] * D + tid];
    }
}

// ---------------------------------------------------------------------------
extern "C" void kernel_launch(void* const* d_in, const int* in_sizes, int n_in,
                              void* d_out, int out_size) {
    const int*   X_user_id = (const int*)d_in[0];
    const float* user_emb  = (const float*)d_in[1];
    const float* src       = (const float*)d_in[2];
    const float* Wcm       = (const float*)d_in[3];
    const float* W1        = (const float*)d_in[4];
    const float* A_us      = (const float*)d_in[5];
    float* out = (float*)d_out;

    cudaFuncSetAttribute(attn_kernel, cudaFuncAttributeMaxDynamicSharedMemorySize, SMEM_BYTES);

    zero_kernel<<<(NROWS * D + 1023) / 1024, 1024>>>();
    qproj_kernel<<<B / 8, 256>>>(X_user_id, user_emb, Wcm);
    convert_kernel<<<(SPAD * 32 + 255) / 256, 256>>>(src);
    attn_kernel<<<dim3(KSPLIT, NROWS / 64), 128, SMEM_BYTES>>>(X_user_id, A_us);
    final_kernel<<<B / 8, 128>>>(X_user_id, user_emb, W1, out);
}

// round 7
// speedup vs baseline: 17.1295x; 1.1563x over previous
#include <cuda_runtime.h>
#include <cuda_bf16.h>
#include <cstdint>
#include <math.h>

#define B 1024
#define S 50000
#define SPAD 50048
#define D 128
#define H 8
#define NROWS (B*H)          // 8192 rows (user,head)
#define KSPLIT 8
#define NT64 782             // SPAD/64 tiles
#define TPT ((NT64 + KSPLIT - 1)/KSPLIT)   // 98 tiles per split
#define PITCH 272            // smem row pitch bytes (136 bf16) — conflict-free ldmatrix

// ---------------- device scratch ----------------
__device__ __nv_bfloat16 g_Qb[NROWS * D];     // Q rows bf16, pre-scaled by log2e/sqrt(D)
__device__ __nv_bfloat16 g_Mb[SPAD * D];      // source emb bf16 (pad rows zero)
__device__ float g_Num[NROWS * D];            // raw numerators
__device__ float g_Den[NROWS];                // denominators

// ---------------- helpers ----------------
__device__ __forceinline__ uint32_t smem_u32(const void* p) {
    uint32_t a; asm("{ .reg .u64 t; cvta.to.shared.u64 t, %1; cvt.u32.u64 %0, t; }" : "=r"(a) : "l"(p));
    return a;
}
__device__ __forceinline__ void cp16(uint32_t dst, const void* src) {
    asm volatile("cp.async.cg.shared.global [%0], [%1], 16;" :: "r"(dst), "l"(src));
}
#define CP_COMMIT() asm volatile("cp.async.commit_group;")
#define CP_WAIT0()  asm volatile("cp.async.wait_group 0;")

__device__ __forceinline__ void ldsm4(uint32_t& r0, uint32_t& r1, uint32_t& r2, uint32_t& r3, uint32_t a) {
    asm volatile("ldmatrix.sync.aligned.m8n8.x4.shared.b16 {%0,%1,%2,%3}, [%4];"
                 : "=r"(r0), "=r"(r1), "=r"(r2), "=r"(r3) : "r"(a));
}
__device__ __forceinline__ void ldsm4t(uint32_t& r0, uint32_t& r1, uint32_t& r2, uint32_t& r3, uint32_t a) {
    asm volatile("ldmatrix.sync.aligned.m8n8.x4.trans.shared.b16 {%0,%1,%2,%3}, [%4];"
                 : "=r"(r0), "=r"(r1), "=r"(r2), "=r"(r3) : "r"(a));
}
__device__ __forceinline__ void mma16816(float* c, uint32_t a0, uint32_t a1, uint32_t a2, uint32_t a3,
                                         uint32_t b0, uint32_t b1) {
    asm volatile("mma.sync.aligned.m16n8k16.row.col.f32.bf16.bf16.f32 "
                 "{%0,%1,%2,%3},{%4,%5,%6,%7},{%8,%9},{%0,%1,%2,%3};"
                 : "+f"(c[0]), "+f"(c[1]), "+f"(c[2]), "+f"(c[3])
                 : "r"(a0), "r"(a1), "r"(a2), "r"(a3), "r"(b0), "r"(b1));
}
// 2^x via MUFU.EX2 (single SASS instruction)
__device__ __forceinline__ float ex2(float x) {
    float r;
    asm("ex2.approx.ftz.f32 %0, %1;" : "=f"(r) : "f"(x));
    return r;
}
__device__ __forceinline__ uint32_t packbf2(float lo, float hi) {
    __nv_bfloat162 v = __floats2bfloat162_rn(lo, hi);
    return *(uint32_t*)&v;
}

// ---------------- Kernel 0: zero accumulators ----------------
__global__ void zero_kernel() {
    int i = blockIdx.x * blockDim.x + threadIdx.x;
    if (i < NROWS * D) g_Num[i] = 0.f;
    if (i < NROWS) g_Den[i] = 0.f;
}

// ---------------- Kernel 1: Q projection -> bf16 ----------------
// Q pre-scaled by log2e/sqrt(D): since A>=0, exp(relu(q.m)*a) = 2^(relu((q*log2e).m)*a)
__global__ __launch_bounds__(256)
void qproj_kernel(const int* __restrict__ uid,
                  const float* __restrict__ user_emb,
                  const float* __restrict__ Wcm) {
    __shared__ float sX[8 * 132];
    __shared__ int sU[8];
    int bu = blockIdx.x * 8;
    int tid = threadIdx.x;
    if (tid < 8) sU[tid] = uid[bu + tid];
    __syncthreads();
    for (int i = tid; i < 8 * 128; i += 256) {
        int u = i >> 7, d = i & 127;
        sX[u * 132 + d] = user_emb[(size_t)sU[u] * D + d];
    }
    __syncthreads();
    const float scale = 1.4426950408889634f * rsqrtf(128.f);
    for (int o = tid; o < H * D; o += 256) {
        int h = o >> 7, e = o & 127;
        const float* w = Wcm + h * D * D + e;
        float acc[8];
#pragma unroll
        for (int u = 0; u < 8; u++) acc[u] = 0.f;
#pragma unroll 4
        for (int d = 0; d < D; d++) {
            float wv = w[d * D];
#pragma unroll
            for (int u = 0; u < 8; u++) acc[u] += sX[u * 132 + d] * wv;
        }
#pragma unroll
        for (int u = 0; u < 8; u++)
            g_Qb[((size_t)(bu + u) * H + h) * D + e] = __float2bfloat16(acc[u] * scale);
    }
}

// ---------------- Kernel 2: source emb fp32 -> bf16 (pad rows zero) ----------------
__global__ __launch_bounds__(256)
void convert_kernel(const float* __restrict__ src) {
    long long i = (long long)blockIdx.x * blockDim.x + threadIdx.x;   // one float4 per thread
    if (i >= (long long)SPAD * 32) return;
    int s = (int)(i >> 5);
    int c = (int)(i & 31) << 2;
    float4 v = make_float4(0.f, 0.f, 0.f, 0.f);
    if (s < S) v = *(const float4*)&src[(size_t)s * D + c];
    *(__nv_bfloat162*)&g_Mb[(size_t)s * D + c]     = __floats2bfloat162_rn(v.x, v.y);
    *(__nv_bfloat162*)&g_Mb[(size_t)s * D + c + 2] = __floats2bfloat162_rn(v.z, v.w);
}

// ---------------- attention tile body ----------------
template<bool TAIL>
__device__ __forceinline__ void tile_body(uint32_t sqA, uint32_t srcb,
                                          const float* a0p, const float* a1p,
                                          int s0c, float (&oacc)[16][4],
                                          float& esum0, float& esum1,
                                          uint32_t b1o, uint32_t vo) {
    // ---- GEMM1: P[16 x 64] = Q[16 x 128] . Mtile^T  (P pre-scaled by log2e) ----
    float pa[8][4];
#pragma unroll
    for (int n = 0; n < 8; n++)
#pragma unroll
        for (int q = 0; q < 4; q++) pa[n][q] = 0.f;
#pragma unroll
    for (int k = 0; k < 8; k++) {
        uint32_t q0, q1, q2, q3;
        ldsm4(q0, q1, q2, q3, sqA + k * 32);
#pragma unroll
        for (int j = 0; j < 4; j++) {
            uint32_t b0, b1, b2, b3;
            ldsm4(b0, b1, b2, b3, srcb + b1o + j * (16 * PITCH) + k * 32);
            mma16816(pa[2 * j],     q0, q1, q2, q3, b0, b1);
            mma16816(pa[2 * j + 1], q0, q1, q2, q3, b2, b3);
        }
    }
    // ---- epilogue: e = 2^(relu(p*a))  [FMUL + FMNMX + MUFU.EX2 per value] ----
    uint32_t er[4][4];
#pragma unroll
    for (int n = 0; n < 8; n++) {
        float2 a0 = *(const float2*)(a0p + 8 * n);
        float2 a1 = *(const float2*)(a1p + 8 * n);
        float e00 = ex2(fmaxf(pa[n][0] * a0.x, 0.f));
        float e01 = ex2(fmaxf(pa[n][1] * a0.y, 0.f));
        float e10 = ex2(fmaxf(pa[n][2] * a1.x, 0.f));
        float e11 = ex2(fmaxf(pa[n][3] * a1.y, 0.f));
        if (TAIL) {
            bool v0 = (s0c + 8 * n) < S;
            bool v1 = (s0c + 8 * n + 1) < S;
            e00 = v0 ? e00 : 0.f;  e01 = v1 ? e01 : 0.f;
            e10 = v0 ? e10 : 0.f;  e11 = v1 ? e11 : 0.f;
        }
        esum0 += e00 + e01;
        esum1 += e10 + e11;
        er[n >> 1][(n & 1) * 2 + 0] = packbf2(e00, e01);
        er[n >> 1][(n & 1) * 2 + 1] = packbf2(e10, e11);
    }
    // ---- GEMM2: O[16 x 128] += E[16 x 64] . Mtile ----
#pragma unroll
    for (int kk = 0; kk < 4; kk++) {
#pragma unroll
        for (int j = 0; j < 8; j++) {
            uint32_t v0, v1, v2, v3;
            ldsm4t(v0, v1, v2, v3, srcb + vo + kk * (16 * PITCH) + j * 32);
            mma16816(oacc[2 * j],     er[kk][0], er[kk][1], er[kk][2], er[kk][3], v0, v1);
            mma16816(oacc[2 * j + 1], er[kk][0], er[kk][1], er[kk][2], er[kk][3], v2, v3);
        }
    }
}

// ---------------- Kernel 3: fused attention (mma.sync bf16) ----------------
// grid (KSPLIT, 128); 128 threads. Block = 64 rows (8 users x 8 heads) x S-chunk.
#define SQ_OFF   0u
#define SRC0_OFF 17408u
#define SRC1_OFF 34816u
#define SA0_OFF  52224u
#define SA1_OFF  54400u
#define SUID_OFF 56576u
#define SMEM_BYTES 56704u

__global__ __launch_bounds__(128, 4)
void attn_kernel(const int* __restrict__ uid, const float* __restrict__ A_us) {
    extern __shared__ char sm[];
    const uint32_t sb = smem_u32(sm);
    const int tid = threadIdx.x;
    const int lane = tid & 31;
    const int w = tid >> 5;
    const int ks = blockIdx.x;
    const int rb = blockIdx.y;
    const int rowbase = rb * 64;
    int* sUid = (int*)(sm + SUID_OFF);

    if (tid < 8) sUid[tid] = uid[rb * 8 + tid];
    __syncthreads();

    // stage Q slab [64 rows][128] bf16 into pitch-272 smem
#pragma unroll
    for (int j = 0; j < 8; j++) {
        int idx = tid + j * 128;
        int row = idx >> 4, ch = idx & 15;
        uint4 v = *(const uint4*)&g_Qb[(size_t)(rowbase + row) * D + ch * 8];
        *(uint4*)(sm + SQ_OFF + row * PITCH + ch * 16) = v;
    }

    const int t0 = ks * TPT;
    const int t1 = min(t0 + TPT, NT64);

    // prefetch tile t0 into buf0
    {
        int s0 = t0 * 64;
#pragma unroll
        for (int j = 0; j < 8; j++) {
            int idx = tid + j * 128;
            int row = idx >> 4, ch = idx & 15;
            cp16(sb + SRC0_OFF + row * PITCH + ch * 16, &g_Mb[(size_t)(s0 + row) * D + ch * 8]);
        }
        int u = tid >> 4, cc = (tid & 15) * 4;
        if (s0 + cc + 4 <= S)
            cp16(sb + SA0_OFF + u * PITCH + cc * 4, &A_us[(size_t)sUid[u] * S + s0 + cc]);
        CP_COMMIT();
    }

    // per-thread ldmatrix address components
    const uint32_t sqA = sb + SQ_OFF + (16 * w + (lane & 15)) * PITCH + (lane >> 4) * 16;
    const uint32_t b1o = (((lane >> 4) & 1) * 8 + (lane & 7)) * PITCH + ((lane >> 3) & 1) * 16;
    const uint32_t vo  = (((lane >> 3) & 1) * 8 + (lane & 7)) * PITCH + (lane >> 4) * 16;
    const int cb = 2 * (lane & 3);

    float oacc[16][4];
#pragma unroll
    for (int n = 0; n < 16; n++)
#pragma unroll
        for (int q = 0; q < 4; q++) oacc[n][q] = 0.f;
    float esum0 = 0.f, esum1 = 0.f;

    for (int t = t0; t < t1; ++t) {
        int bufi = (t - t0) & 1;
        CP_WAIT0();
        __syncthreads();
        if (t + 1 < t1) {   // prefetch next tile into the other buffer
            int s0n = (t + 1) * 64;
            uint32_t srcn = sb + (bufi ? SRC0_OFF : SRC1_OFF);
            uint32_t san  = sb + (bufi ? SA0_OFF : SA1_OFF);
#pragma unroll
            for (int j = 0; j < 8; j++) {
                int idx = tid + j * 128;
                int row = idx >> 4, ch = idx & 15;
                cp16(srcn + row * PITCH + ch * 16, &g_Mb[(size_t)(s0n + row) * D + ch * 8]);
            }
            int u = tid >> 4, cc = (tid & 15) * 4;
            if (s0n + cc + 4 <= S)
                cp16(san + u * PITCH + cc * 4, &A_us[(size_t)sUid[u] * S + s0n + cc]);
            CP_COMMIT();
        }
        uint32_t srcb = sb + (bufi ? SRC1_OFF : SRC0_OFF);
        const float* sAa = (const float*)(sm + (bufi ? SA1_OFF : SA0_OFF));
        const float* a0p = sAa + (2 * w) * 68 + cb;       // user 2w  (rows 0-7 of warp slab)
        const float* a1p = a0p + 68;                      // user 2w+1 (rows 8-15)
        int s0 = t * 64;
        if (t == NT64 - 1)
            tile_body<true >(sqA, srcb, a0p, a1p, s0 + cb, oacc, esum0, esum1, b1o, vo);
        else
            tile_body<false>(sqA, srcb, a0p, a1p, s0 + cb, oacc, esum0, esum1, b1o, vo);
    }

    // ---- denominators: reduce over the 4 lanes sharing each row ----
    esum0 += __shfl_xor_sync(0xffffffffu, esum0, 1);
    esum0 += __shfl_xor_sync(0xffffffffu, esum0, 2);
    esum1 += __shfl_xor_sync(0xffffffffu, esum1, 1);
    esum1 += __shfl_xor_sync(0xffffffffu, esum1, 2);
    int r0g = rowbase + 16 * w + (lane >> 2);
    if ((lane & 3) == 0) {
        atomicAdd(&g_Den[r0g], esum0);
        atomicAdd(&g_Den[r0g + 8], esum1);
    }
    // ---- raw numerators ----
#pragma unroll
    for (int nn = 0; nn < 16; nn++) {
        int c = 8 * nn + cb;
        float* d0 = &g_Num[(size_t)r0g * D + c];
        float* d1 = &g_Num[(size_t)(r0g + 8) * D + c];
        atomicAdd(d0,     oacc[nn][0]);
        atomicAdd(d0 + 1, oacc[nn][1]);
        atomicAdd(d1,     oacc[nn][2]);
        atomicAdd(d1 + 1, oacc[nn][3]);
    }
}

// ---------------- Kernel 4: normalize, W1, elu, +Xu ----------------
__global__ __launch_bounds__(128)
void final_kernel(const int* __restrict__ uid,
                  const float* __restrict__ user_emb,
                  const float* __restrict__ W1,
                  float* __restrict__ out) {
    __shared__ float smc[8 * 1024];
    int bu = blockIdx.x * 8;
    int tid = threadIdx.x;
    for (int i = tid; i < 8 * 1024; i += 128) {
        int uu = i >> 10, idx = i & 1023;
        smc[i] = g_Num[(size_t)(bu + uu) * 1024 + idx] / g_Den[(bu + uu) * 8 + (idx >> 7)];
    }
    __syncthreads();
    float acc[8];
#pragma unroll
    for (int uu = 0; uu < 8; uu++) acc[uu] = 0.f;
#pragma unroll 4
    for (int i = 0; i < 1024; i++) {
        float wv = W1[i * D + tid];
#pragma unroll
        for (int uu = 0; uu < 8; uu++) acc[uu] += smc[uu * 1024 + i] * wv;
    }
#pragma unroll
    for (int uu = 0; uu < 8; uu++) {
        float v = acc[uu];
        float e = v > 0.f ? v : expm1f(v);
        out[(size_t)(bu + uu) * D + tid] = e + user_emb[(size_t)uid[bu + uu] * D + tid];
    }
}

// ---------------------------------------------------------------------------
extern "C" void kernel_launch(void* const* d_in, const int* in_sizes, int n_in,
                              void* d_out, int out_size) {
    const int*   X_user_id = (const int*)d_in[0];
    const float* user_emb  = (const float*)d_in[1];
    const float* src       = (const float*)d_in[2];
    const float* Wcm       = (const float*)d_in[3];
    const float* W1        = (const float*)d_in[4];
    const float* A_us      = (const float*)d_in[5];
    float* out = (float*)d_out;

    cudaFuncSetAttribute(attn_kernel, cudaFuncAttributeMaxDynamicSharedMemorySize, SMEM_BYTES);

    zero_kernel<<<(NROWS * D + 1023) / 1024, 1024>>>();
    qproj_kernel<<<B / 8, 256>>>(X_user_id, user_emb, Wcm);
    convert_kernel<<<(SPAD * 32 + 255) / 256, 256>>>(src);
    attn_kernel<<<dim3(KSPLIT, NROWS / 64), 128, SMEM_BYTES>>>(X_user_id, A_us);
    final_kernel<<<B / 8, 128>>>(X_user_id, user_emb, W1, out);
}

// round 8
// speedup vs baseline: 22.1837x; 1.2951x over previous
#include <cuda_runtime.h>
#include <cuda_bf16.h>
#include <cstdint>
#include <math.h>

#define B 1024
#define S 50000
#define SPAD 50048
#define D 128
#define H 8
#define NROWS (B*H)          // 8192 rows (user,head)
#define KSPLIT 23
#define NT64 782             // SPAD/64 tiles (= 23 * 34 exactly)
#define TPT 34               // tiles per split
#define PITCH 272            // smem row pitch bytes (136 bf16) — conflict-free ldmatrix

// ---------------- device scratch ----------------
__device__ __nv_bfloat16 g_Qb[NROWS * D];        // Q rows bf16, pre-scaled by log2e/sqrt(D)
__device__ __nv_bfloat16 g_Mb[SPAD * D];         // source emb bf16 (pad rows zero)
__device__ float g_NumS[(size_t)KSPLIT * NROWS * D];   // per-split raw numerators (96.5 MB)
__device__ float g_DenS[KSPLIT * NROWS];               // per-split denominators

// ---------------- helpers ----------------
__device__ __forceinline__ uint32_t smem_u32(const void* p) {
    uint32_t a; asm("{ .reg .u64 t; cvta.to.shared.u64 t, %1; cvt.u32.u64 %0, t; }" : "=r"(a) : "l"(p));
    return a;
}
__device__ __forceinline__ void cp16(uint32_t dst, const void* src) {
    asm volatile("cp.async.cg.shared.global [%0], [%1], 16;" :: "r"(dst), "l"(src));
}
#define CP_COMMIT() asm volatile("cp.async.commit_group;")
#define CP_WAIT0()  asm volatile("cp.async.wait_group 0;")

__device__ __forceinline__ void ldsm4(uint32_t& r0, uint32_t& r1, uint32_t& r2, uint32_t& r3, uint32_t a) {
    asm volatile("ldmatrix.sync.aligned.m8n8.x4.shared.b16 {%0,%1,%2,%3}, [%4];"
                 : "=r"(r0), "=r"(r1), "=r"(r2), "=r"(r3) : "r"(a));
}
__device__ __forceinline__ void ldsm4t(uint32_t& r0, uint32_t& r1, uint32_t& r2, uint32_t& r3, uint32_t a) {
    asm volatile("ldmatrix.sync.aligned.m8n8.x4.trans.shared.b16 {%0,%1,%2,%3}, [%4];"
                 : "=r"(r0), "=r"(r1), "=r"(r2), "=r"(r3) : "r"(a));
}
__device__ __forceinline__ void mma16816(float* c, uint32_t a0, uint32_t a1, uint32_t a2, uint32_t a3,
                                         uint32_t b0, uint32_t b1) {
    asm volatile("mma.sync.aligned.m16n8k16.row.col.f32.bf16.bf16.f32 "
                 "{%0,%1,%2,%3},{%4,%5,%6,%7},{%8,%9},{%0,%1,%2,%3};"
                 : "+f"(c[0]), "+f"(c[1]), "+f"(c[2]), "+f"(c[3])
                 : "r"(a0), "r"(a1), "r"(a2), "r"(a3), "r"(b0), "r"(b1));
}
// 2^x via MUFU.EX2 (single SASS instruction)
__device__ __forceinline__ float ex2(float x) {
    float r;
    asm("ex2.approx.ftz.f32 %0, %1;" : "=f"(r) : "f"(x));
    return r;
}
__device__ __forceinline__ uint32_t packbf2(float lo, float hi) {
    __nv_bfloat162 v = __floats2bfloat162_rn(lo, hi);
    return *(uint32_t*)&v;
}

// ---------------- Kernel 1: Q projection -> bf16 ----------------
// Q pre-scaled by log2e/sqrt(D): since A>=0, exp(relu(q.m)*a) = 2^(relu((q*log2e).m)*a)
__global__ __launch_bounds__(256)
void qproj_kernel(const int* __restrict__ uid,
                  const float* __restrict__ user_emb,
                  const float* __restrict__ Wcm) {
    __shared__ float sX[8 * 132];
    __shared__ int sU[8];
    int bu = blockIdx.x * 8;
    int tid = threadIdx.x;
    if (tid < 8) sU[tid] = uid[bu + tid];
    __syncthreads();
    for (int i = tid; i < 8 * 128; i += 256) {
        int u = i >> 7, d = i & 127;
        sX[u * 132 + d] = user_emb[(size_t)sU[u] * D + d];
    }
    __syncthreads();
    const float scale = 1.4426950408889634f * rsqrtf(128.f);
    int o = blockIdx.y * 256 + tid;       // one output (h,e) per thread
    int h = o >> 7, e = o & 127;
    const float* w = Wcm + h * D * D + e;
    float acc[8];
#pragma unroll
    for (int u = 0; u < 8; u++) acc[u] = 0.f;
#pragma unroll 4
    for (int d = 0; d < D; d++) {
        float wv = w[d * D];
#pragma unroll
        for (int u = 0; u < 8; u++) acc[u] += sX[u * 132 + d] * wv;
    }
#pragma unroll
    for (int u = 0; u < 8; u++)
        g_Qb[((size_t)(bu + u) * H + h) * D + e] = __float2bfloat16(acc[u] * scale);
}

// ---------------- Kernel 2: source emb fp32 -> bf16 (pad rows zero) ----------------
__global__ __launch_bounds__(256)
void convert_kernel(const float* __restrict__ src) {
    long long i = (long long)blockIdx.x * blockDim.x + threadIdx.x;   // one float4 per thread
    if (i >= (long long)SPAD * 32) return;
    int s = (int)(i >> 5);
    int c = (int)(i & 31) << 2;
    float4 v = make_float4(0.f, 0.f, 0.f, 0.f);
    if (s < S) v = *(const float4*)&src[(size_t)s * D + c];
    *(__nv_bfloat162*)&g_Mb[(size_t)s * D + c]     = __floats2bfloat162_rn(v.x, v.y);
    *(__nv_bfloat162*)&g_Mb[(size_t)s * D + c + 2] = __floats2bfloat162_rn(v.z, v.w);
}

// ---------------- attention tile body: 32 rows x 64 src x 128 d per warp ----------------
template<bool TAIL>
__device__ __forceinline__ void tile_body(uint32_t sqA0, uint32_t srcb,
                                          const float* aP00, const float* aP01,
                                          const float* aP10, const float* aP11,
                                          int s0c, float (&oacc)[2][16][4],
                                          float (&esum)[2][2],
                                          uint32_t b1o, uint32_t vo) {
    // ---- GEMM1: P[32 x 64] = Q[32 x 128] . Mtile^T  (B frags shared by both M-halves) ----
    float pa[2][8][4];
#pragma unroll
    for (int mh = 0; mh < 2; mh++)
#pragma unroll
        for (int n = 0; n < 8; n++)
#pragma unroll
            for (int q = 0; q < 4; q++) pa[mh][n][q] = 0.f;
#pragma unroll
    for (int k = 0; k < 8; k++) {
        uint32_t q00, q01, q02, q03, q10, q11, q12, q13;
        ldsm4(q00, q01, q02, q03, sqA0 + k * 32);
        ldsm4(q10, q11, q12, q13, sqA0 + 16 * PITCH + k * 32);
#pragma unroll
        for (int j = 0; j < 4; j++) {
            uint32_t b0, b1, b2, b3;
            ldsm4(b0, b1, b2, b3, srcb + b1o + j * (16 * PITCH) + k * 32);
            mma16816(pa[0][2 * j],     q00, q01, q02, q03, b0, b1);
            mma16816(pa[0][2 * j + 1], q00, q01, q02, q03, b2, b3);
            mma16816(pa[1][2 * j],     q10, q11, q12, q13, b0, b1);
            mma16816(pa[1][2 * j + 1], q10, q11, q12, q13, b2, b3);
        }
    }
    // ---- epilogue: e = 2^(relu(p*a)) ----
    uint32_t er[2][4][4];
#pragma unroll
    for (int mh = 0; mh < 2; mh++) {
        const float* ap0 = mh ? aP10 : aP00;
        const float* ap1 = mh ? aP11 : aP01;
#pragma unroll
        for (int n = 0; n < 8; n++) {
            float2 a0 = *(const float2*)(ap0 + 8 * n);
            float2 a1 = *(const float2*)(ap1 + 8 * n);
            float e00 = ex2(fmaxf(pa[mh][n][0] * a0.x, 0.f));
            float e01 = ex2(fmaxf(pa[mh][n][1] * a0.y, 0.f));
            float e10 = ex2(fmaxf(pa[mh][n][2] * a1.x, 0.f));
            float e11 = ex2(fmaxf(pa[mh][n][3] * a1.y, 0.f));
            if (TAIL) {
                bool v0 = (s0c + 8 * n) < S;
                bool v1 = (s0c + 8 * n + 1) < S;
                e00 = v0 ? e00 : 0.f;  e01 = v1 ? e01 : 0.f;
                e10 = v0 ? e10 : 0.f;  e11 = v1 ? e11 : 0.f;
            }
            esum[mh][0] += e00 + e01;
            esum[mh][1] += e10 + e11;
            er[mh][n >> 1][(n & 1) * 2 + 0] = packbf2(e00, e01);
            er[mh][n >> 1][(n & 1) * 2 + 1] = packbf2(e10, e11);
        }
    }
    // ---- GEMM2: O[32 x 128] += E[32 x 64] . Mtile  (V frags shared by both M-halves) ----
#pragma unroll
    for (int kk = 0; kk < 4; kk++) {
#pragma unroll
        for (int j = 0; j < 8; j++) {
            uint32_t v0, v1, v2, v3;
            ldsm4t(v0, v1, v2, v3, srcb + vo + kk * (16 * PITCH) + j * 32);
            mma16816(oacc[0][2 * j],     er[0][kk][0], er[0][kk][1], er[0][kk][2], er[0][kk][3], v0, v1);
            mma16816(oacc[0][2 * j + 1], er[0][kk][0], er[0][kk][1], er[0][kk][2], er[0][kk][3], v2, v3);
            mma16816(oacc[1][2 * j],     er[1][kk][0], er[1][kk][1], er[1][kk][2], er[1][kk][3], v0, v1);
            mma16816(oacc[1][2 * j + 1], er[1][kk][0], er[1][kk][1], er[1][kk][2], er[1][kk][3], v2, v3);
        }
    }
}

// ---------------- Kernel 3: fused attention (mma.sync bf16) ----------------
// grid (KSPLIT, 64); 128 threads. CTA = 128 rows (16 users); warp = 32 rows (4 users).
#define SQ_OFF   0u
#define SRC0_OFF 34816u
#define SRC1_OFF 52224u
#define SA0_OFF  69632u
#define SA1_OFF  73984u
#define SUID_OFF 78336u
#define SMEM_BYTES 78400u

__global__ __launch_bounds__(128, 2)
void attn_kernel(const int* __restrict__ uid, const float* __restrict__ A_us) {
    extern __shared__ char sm[];
    const uint32_t sb = smem_u32(sm);
    const int tid = threadIdx.x;
    const int lane = tid & 31;
    const int w = tid >> 5;
    const int ks = blockIdx.x;
    const int rb = blockIdx.y;
    const int rowbase = rb * 128;       // 128 global rows per CTA
    int* sUid = (int*)(sm + SUID_OFF);

    if (tid < 16) sUid[tid] = uid[rb * 16 + tid];
    __syncthreads();

    // stage Q slab [128 rows][128] bf16 into pitch-272 smem
#pragma unroll
    for (int j = 0; j < 16; j++) {
        int idx = tid + j * 128;
        int row = idx >> 4, ch = idx & 15;
        uint4 v = *(const uint4*)&g_Qb[(size_t)(rowbase + row) * D + ch * 8];
        *(uint4*)(sm + SQ_OFF + row * PITCH + ch * 16) = v;
    }

    const int t0 = ks * TPT;
    const int t1 = t0 + TPT;

    // prefetch tile t0 into buf0
    {
        int s0 = t0 * 64;
#pragma unroll
        for (int j = 0; j < 8; j++) {
            int idx = tid + j * 128;
            int row = idx >> 4, ch = idx & 15;
            cp16(sb + SRC0_OFF + row * PITCH + ch * 16, &g_Mb[(size_t)(s0 + row) * D + ch * 8]);
        }
#pragma unroll
        for (int j = 0; j < 2; j++) {
            int idx = tid + j * 128;
            int u = idx >> 4, cc = (idx & 15) * 4;
            if (s0 + cc + 4 <= S)
                cp16(sb + SA0_OFF + u * PITCH + cc * 4, &A_us[(size_t)sUid[u] * S + s0 + cc]);
        }
        CP_COMMIT();
    }

    // per-thread ldmatrix address components
    const uint32_t sqA0 = sb + SQ_OFF + (32 * w + (lane & 15)) * PITCH + (lane >> 4) * 16;
    const uint32_t b1o = (((lane >> 4) & 1) * 8 + (lane & 7)) * PITCH + ((lane >> 3) & 1) * 16;
    const uint32_t vo  = (((lane >> 3) & 1) * 8 + (lane & 7)) * PITCH + (lane >> 4) * 16;
    const int cb = 2 * (lane & 3);

    float oacc[2][16][4];
#pragma unroll
    for (int mh = 0; mh < 2; mh++)
#pragma unroll
        for (int n = 0; n < 16; n++)
#pragma unroll
            for (int q = 0; q < 4; q++) oacc[mh][n][q] = 0.f;
    float esum[2][2];
    esum[0][0] = esum[0][1] = esum[1][0] = esum[1][1] = 0.f;

    for (int t = t0; t < t1; ++t) {
        int bufi = (t - t0) & 1;
        CP_WAIT0();
        __syncthreads();
        if (t + 1 < t1) {   // prefetch next tile into the other buffer
            int s0n = (t + 1) * 64;
            uint32_t srcn = sb + (bufi ? SRC0_OFF : SRC1_OFF);
            uint32_t san  = sb + (bufi ? SA0_OFF : SA1_OFF);
#pragma unroll
            for (int j = 0; j < 8; j++) {
                int idx = tid + j * 128;
                int row = idx >> 4, ch = idx & 15;
                cp16(srcn + row * PITCH + ch * 16, &g_Mb[(size_t)(s0n + row) * D + ch * 8]);
            }
#pragma unroll
            for (int j = 0; j < 2; j++) {
                int idx = tid + j * 128;
                int u = idx >> 4, cc = (idx & 15) * 4;
                if (s0n + cc + 4 <= S)
                    cp16(san + u * PITCH + cc * 4, &A_us[(size_t)sUid[u] * S + s0n + cc]);
            }
            CP_COMMIT();
        }
        uint32_t srcb = sb + (bufi ? SRC1_OFF : SRC0_OFF);
        const float* sAa = (const float*)(sm + (bufi ? SA1_OFF : SA0_OFF));
        // warp w owns users 4w..4w+3: mh0 -> users 4w,4w+1 ; mh1 -> users 4w+2,4w+3
        const float* aP00 = sAa + (4 * w + 0) * 68 + cb;
        const float* aP01 = sAa + (4 * w + 1) * 68 + cb;
        const float* aP10 = sAa + (4 * w + 2) * 68 + cb;
        const float* aP11 = sAa + (4 * w + 3) * 68 + cb;
        int s0 = t * 64;
        if (t == NT64 - 1)
            tile_body<true >(sqA0, srcb, aP00, aP01, aP10, aP11, s0 + cb, oacc, esum, b1o, vo);
        else
            tile_body<false>(sqA0, srcb, aP00, aP01, aP10, aP11, s0 + cb, oacc, esum, b1o, vo);
    }

    // ---- denominators: reduce over the 4 lanes sharing each row (non-atomic per-split) ----
#pragma unroll
    for (int mh = 0; mh < 2; mh++)
#pragma unroll
        for (int hh = 0; hh < 2; hh++) {
            esum[mh][hh] += __shfl_xor_sync(0xffffffffu, esum[mh][hh], 1);
            esum[mh][hh] += __shfl_xor_sync(0xffffffffu, esum[mh][hh], 2);
        }
    int r0 = rowbase + 32 * w + (lane >> 2);
    if ((lane & 3) == 0) {
        float* gD = g_DenS + ks * NROWS;
        gD[r0]      = esum[0][0];
        gD[r0 + 8]  = esum[0][1];
        gD[r0 + 16] = esum[1][0];
        gD[r0 + 24] = esum[1][1];
    }
    // ---- raw numerators (non-atomic per-split stores) ----
    float* gN = g_NumS + (size_t)ks * NROWS * D;
#pragma unroll
    for (int mh = 0; mh < 2; mh++) {
        int rr = r0 + 16 * mh;
#pragma unroll
        for (int nf = 0; nf < 16; nf++) {
            int c = 8 * nf + cb;
            *(float2*)&gN[(size_t)rr * D + c]       = make_float2(oacc[mh][nf][0], oacc[mh][nf][1]);
            *(float2*)&gN[(size_t)(rr + 8) * D + c] = make_float2(oacc[mh][nf][2], oacc[mh][nf][3]);
        }
    }
}

// ---------------- Kernel 4: combine splits, normalize, W1, elu, +Xu ----------------
__global__ __launch_bounds__(128)
void final_kernel(const int* __restrict__ uid,
                  const float* __restrict__ user_emb,
                  const float* __restrict__ W1,
                  float* __restrict__ out) {
    __shared__ float smc[8 * 1024];
    __shared__ float sden[64];
    int bu = blockIdx.x * 8;
    int tid = threadIdx.x;
    if (tid < 64) {
        float s = 0.f;
#pragma unroll
        for (int k = 0; k < KSPLIT; k++) s += g_DenS[k * NROWS + blockIdx.x * 64 + tid];
        sden[tid] = 1.f / s;
    }
    __syncthreads();
    for (int ii = tid; ii < 2048; ii += 128) {           // float4 positions
        size_t off = (size_t)blockIdx.x * 8192 + (size_t)ii * 4;
        float4 a = make_float4(0.f, 0.f, 0.f, 0.f);
#pragma unroll
        for (int k = 0; k < KSPLIT; k++) {
            float4 v = *(const float4*)&g_NumS[(size_t)k * NROWS * D + off];
            a.x += v.x; a.y += v.y; a.z += v.z; a.w += v.w;
        }
        float inv = sden[ii >> 5];
        smc[ii * 4 + 0] = a.x * inv;
        smc[ii * 4 + 1] = a.y * inv;
        smc[ii * 4 + 2] = a.z * inv;
        smc[ii * 4 + 3] = a.w * inv;
    }
    __syncthreads();
    float acc[8];
#pragma unroll
    for (int uu = 0; uu < 8; uu++) acc[uu] = 0.f;
#pragma unroll 4
    for (int i = 0; i < 1024; i++) {
        float wv = W1[i * D + tid];
#pragma unroll
        for (int uu = 0; uu < 8; uu++) acc[uu] += smc[uu * 1024 + i] * wv;
    }
#pragma unroll
    for (int uu = 0; uu < 8; uu++) {
        float v = acc[uu];
        float e = v > 0.f ? v : expm1f(v);
        out[(size_t)(bu + uu) * D + tid] = e + user_emb[(size_t)uid[bu + uu] * D + tid];
    }
}

// ---------------------------------------------------------------------------
extern "C" void kernel_launch(void* const* d_in, const int* in_sizes, int n_in,
                              void* d_out, int out_size) {
    const int*   X_user_id = (const int*)d_in[0];
    const float* user_emb  = (const float*)d_in[1];
    const float* src       = (const float*)d_in[2];
    const float* Wcm       = (const float*)d_in[3];
    const float* W1        = (const float*)d_in[4];
    const float* A_us      = (const float*)d_in[5];
    float* out = (float*)d_out;

    cudaFuncSetAttribute(attn_kernel, cudaFuncAttributeMaxDynamicSharedMemorySize, SMEM_BYTES);

    qproj_kernel<<<dim3(B / 8, 4), 256>>>(X_user_id, user_emb, Wcm);
    convert_kernel<<<(SPAD * 32 + 255) / 256, 256>>>(src);
    attn_kernel<<<dim3(KSPLIT, NROWS / 128), 128, SMEM_BYTES>>>(X_user_id, A_us);
    final_kernel<<<B / 8, 128>>>(X_user_id, user_emb, W1, out);
}